// round 11
// baseline (speedup 1.0000x reference)
#include <cuda_runtime.h>
#include <cuda_bf16.h>
#include <cstdint>
#include <cstddef>
#include <math.h>

// Problem constants
#define B_ 4
#define S_ 4096
#define D_ 512
#define N_ 512
#define M_ (B_ * S_)          // 16384
#define K_ 512
#define CHUNKS 64
#define CL (S_ / CHUNKS)      // 64

// ---------------- scratch (device globals; runtime alloc forbidden) --------
__device__ float g_xgate[(size_t)M_ * D_];
__device__ float g_s[(size_t)M_ * N_];
__device__ float g_decay[N_];
__device__ float g_chunkf[(size_t)B_ * CHUNKS * N_];
__device__ float g_init[(size_t)B_ * CHUNKS * N_];

// bf16 hi/lo activation buffers (ping-pong between GEMMs) and weight splits
__device__ __nv_bfloat16 g_ah[(size_t)M_ * K_];
__device__ __nv_bfloat16 g_al[(size_t)M_ * K_];
__device__ __nv_bfloat16 g_bh[(size_t)M_ * K_];
__device__ __nv_bfloat16 g_bl[(size_t)M_ * K_];
__device__ __nv_bfloat16 g_wgh[K_ * K_], g_wgl[K_ * K_];
__device__ __nv_bfloat16 g_wsph[K_ * K_], g_wspl[K_ * K_];
__device__ __nv_bfloat16 g_wspth[K_ * K_], g_wsptl[K_ * K_];
__device__ __nv_bfloat16 g_woh[K_ * K_], g_wol[K_ * K_];

// ---------------------------------------------------------------------------
// decay[d] = exp( mean_k( -exp(A_log[d,k]) ) )
// ---------------------------------------------------------------------------
__global__ void decay_kernel(const float* __restrict__ A_log) {
    int d = blockIdx.x;
    float sum = 0.f;
    for (int k = threadIdx.x; k < N_; k += 256)
        sum += -expf(A_log[d * N_ + k]);
    __shared__ float red[256];
    red[threadIdx.x] = sum;
    __syncthreads();
    for (int s = 128; s > 0; s >>= 1) {
        if (threadIdx.x < s) red[threadIdx.x] += red[threadIdx.x + s];
        __syncthreads();
    }
    if (threadIdx.x == 0) g_decay[d] = expf(red[0] * (1.0f / (float)N_));
}

// ---------------------------------------------------------------------------
// fp32 -> bf16 hi + bf16 lo   (x ~= hi + lo, residual ~2^-17 relative)
// ---------------------------------------------------------------------------
__device__ __forceinline__ void split2(float v, __nv_bfloat16& h, __nv_bfloat16& l) {
    h = __float2bfloat16_rn(v);
    l = __float2bfloat16_rn(v - __bfloat162float(h));
}

__device__ __forceinline__ void split4_store(const float4 v,
                                             __nv_bfloat16* __restrict__ h,
                                             __nv_bfloat16* __restrict__ l,
                                             size_t i4) {
    __nv_bfloat16 h0, h1, h2, h3, l0, l1, l2, l3;
    split2(v.x, h0, l0); split2(v.y, h1, l1);
    split2(v.z, h2, l2); split2(v.w, h3, l3);
    __nv_bfloat162* hp = (__nv_bfloat162*)(h + i4 * 4);
    __nv_bfloat162* lp = (__nv_bfloat162*)(l + i4 * 4);
    hp[0] = __nv_bfloat162(h0, h1);
    hp[1] = __nv_bfloat162(h2, h3);
    lp[0] = __nv_bfloat162(l0, l1);
    lp[1] = __nv_bfloat162(l2, l3);
}

// Fused split of the three square weight matrices (one launch instead of 3)
__global__ void weight_split3_kernel(const float* __restrict__ w0,
                                     const float* __restrict__ w1,
                                     const float* __restrict__ w2,
                                     __nv_bfloat16* __restrict__ h0,
                                     __nv_bfloat16* __restrict__ l0,
                                     __nv_bfloat16* __restrict__ h1,
                                     __nv_bfloat16* __restrict__ l1,
                                     __nv_bfloat16* __restrict__ h2,
                                     __nv_bfloat16* __restrict__ l2, int n4) {
    int i = blockIdx.x * blockDim.x + threadIdx.x;
    if (i >= n4) return;
    split4_store(((const float4*)w0)[i], h0, l0, (size_t)i);
    split4_store(((const float4*)w1)[i], h1, l1, (size_t)i);
    split4_store(((const float4*)w2)[i], h2, l2, (size_t)i);
}

// ---------------------------------------------------------------------------
// W_sp [N,D] -> transposed split:  out[d][n] = W_sp[n][d]  as bf16 hi/lo
// ---------------------------------------------------------------------------
__global__ void transpose_split_kernel(const float* __restrict__ in,
                                       __nv_bfloat16* __restrict__ oh,
                                       __nv_bfloat16* __restrict__ ol) {
    __shared__ float tile[32][33];
    int d0 = blockIdx.x * 32;
    int n0 = blockIdx.y * 32;
    int tx = threadIdx.x, ty = threadIdx.y;   // (32,8)
#pragma unroll
    for (int i = 0; i < 32; i += 8)
        tile[ty + i][tx] = in[(size_t)(n0 + ty + i) * K_ + d0 + tx];
    __syncthreads();
#pragma unroll
    for (int i = 0; i < 32; i += 8) {
        float v = tile[tx][ty + i];           // = in[n0+tx][d0+ty+i]
        __nv_bfloat16 h, l;
        split2(v, h, l);
        size_t o = (size_t)(d0 + ty + i) * K_ + n0 + tx;
        oh[o] = h;
        ol[o] = l;
    }
}

// ---------------------------------------------------------------------------
// bf16-split GEMM:  C[m][n] = sum_k A[m][k]*B[n][k], fp32 accum, 3-way split
// (Ah*Bh + Ah*Bl + Al*Bh). Tile 128x128, 256 thr = 8 warps (4m x 2n),
// warp tile 32x64, mma.sync.m16n8k16.bf16, double-buffered smem,
// cp.async (LDGSTS) gmem->smem, ldmatrix (LDSM.x4) operand feeds.
// Static smem: 2 stages x 4 arrays x 6144 B = 49152 B (= 48 KB limit exactly).
// AF32:   A operand fp32 in gmem; loader splits hi/lo on the fly (regs->STS)
// EPI: 0 silu(v+bias) | 1 v+bias | 2 v+dparam[col]*xg[row,col] | 3 v+bias
// WF32:   write fp32 C ; WSPLIT: write bf16 hi/lo split to oh/ol
// ---------------------------------------------------------------------------
#define GBM 128
#define GBN 128
#define GBK 16
#define SMSTRIDE 24   // 16 data + 8 pad bf16 per row (48B rows; LDSM conflict-free)
#define STAGE_BYTES (GBM * SMSTRIDE * 2)

__device__ __forceinline__ void mma16816(float* c, const uint32_t a[4],
                                         uint32_t b0, uint32_t b1) {
    asm volatile(
        "mma.sync.aligned.m16n8k16.row.col.f32.bf16.bf16.f32 "
        "{%0,%1,%2,%3}, {%4,%5,%6,%7}, {%8,%9}, {%0,%1,%2,%3};\n"
        : "+f"(c[0]), "+f"(c[1]), "+f"(c[2]), "+f"(c[3])
        : "r"(a[0]), "r"(a[1]), "r"(a[2]), "r"(a[3]), "r"(b0), "r"(b1));
}

__device__ __forceinline__ void ldsm_x4(uint32_t* r, uint32_t addr) {
    asm volatile(
        "ldmatrix.sync.aligned.m8n8.x4.shared.b16 {%0,%1,%2,%3}, [%4];\n"
        : "=r"(r[0]), "=r"(r[1]), "=r"(r[2]), "=r"(r[3]) : "r"(addr));
}

__device__ __forceinline__ void cpasync16(uint32_t dst, const void* src) {
    asm volatile("cp.async.cg.shared.global [%0], [%1], 16;\n"
                 :: "r"(dst), "l"(src));
}
#define CP_COMMIT() asm volatile("cp.async.commit_group;\n" ::: "memory")
#define CP_WAIT0()  asm volatile("cp.async.wait_group 0;\n" ::: "memory")

template <int EPI, bool WF32, bool WSPLIT, bool AF32>
__global__ void __launch_bounds__(256)
bsgemm_kernel(const void* __restrict__ Ah_or_f32,
              const __nv_bfloat16* __restrict__ Al,
              const __nv_bfloat16* __restrict__ Bh,
              const __nv_bfloat16* __restrict__ Bl,
              const float* __restrict__ bias, const float* __restrict__ dparam,
              const float* __restrict__ xg, float* __restrict__ C,
              __nv_bfloat16* __restrict__ oh, __nv_bfloat16* __restrict__ ol,
              int M, int N) {
    __shared__ __nv_bfloat16 smAh[2][GBM * SMSTRIDE];
    __shared__ __nv_bfloat16 smAl[2][GBM * SMSTRIDE];
    __shared__ __nv_bfloat16 smBh[2][GBN * SMSTRIDE];
    __shared__ __nv_bfloat16 smBl[2][GBN * SMSTRIDE];

    const int t = threadIdx.x;
    const int bm = blockIdx.y * GBM;
    const int bn = blockIdx.x * GBN;

    // loader mapping: 128 rows x 16 k, 8 k-elements (16B) per thread per array
    const int lrow = t >> 1;
    const int lk8 = (t & 1) * 8;
    const __nv_bfloat16* aHp = AF32 ? (const __nv_bfloat16*)0
        : (const __nv_bfloat16*)Ah_or_f32 + (size_t)(bm + lrow) * K_ + lk8;
    const float* aFp = AF32
        ? (const float*)Ah_or_f32 + (size_t)(bm + lrow) * K_ + lk8 : (const float*)0;
    const __nv_bfloat16* aLp = AF32 ? (const __nv_bfloat16*)0
        : Al + (size_t)(bm + lrow) * K_ + lk8;
    const __nv_bfloat16* bHp = Bh + (size_t)(bn + lrow) * K_ + lk8;
    const __nv_bfloat16* bLp = Bl + (size_t)(bn + lrow) * K_ + lk8;
    const int soffB = (lrow * SMSTRIDE + lk8) * 2;   // byte offset in a stage
    const int soff  = lrow * SMSTRIDE + lk8;         // element offset

    // compute mapping
    const int wid = t >> 5;
    const int lane = t & 31;
    const int gid = lane >> 2;        // 0..7
    const int tig = lane & 3;         // 0..3
    const int m_off = (wid & 3) * 32;
    const int n_off = (wid >> 2) * 64;

    // ldmatrix per-lane byte offsets (within one stage)
    const int a_r = lane & 15;
    const int a_k = (lane >> 4) * 8;
    int aoff[2];
#pragma unroll
    for (int mt = 0; mt < 2; mt++)
        aoff[mt] = ((m_off + mt * 16 + a_r) * SMSTRIDE + a_k) * 2;
    const int b_r = (lane & 7) + ((lane >> 4) * 8);
    const int b_k = ((lane >> 3) & 1) * 8;
    int boff[4];
#pragma unroll
    for (int g = 0; g < 4; g++)
        boff[g] = ((n_off + g * 16 + b_r) * SMSTRIDE + b_k) * 2;

    const uint32_t baseAh = (uint32_t)__cvta_generic_to_shared(&smAh[0][0]);
    const uint32_t baseAl = (uint32_t)__cvta_generic_to_shared(&smAl[0][0]);
    const uint32_t baseBh = (uint32_t)__cvta_generic_to_shared(&smBh[0][0]);
    const uint32_t baseBl = (uint32_t)__cvta_generic_to_shared(&smBl[0][0]);

    float c[2][8][4];
#pragma unroll
    for (int mt = 0; mt < 2; mt++)
#pragma unroll
        for (int nt = 0; nt < 8; nt++)
#pragma unroll
            for (int r = 0; r < 4; r++) c[mt][nt][r] = 0.f;

    {   // preload chunk 0 -> stage 0
        if (AF32) {
            float4 f0 = *(const float4*)(aFp);
            float4 f1 = *(const float4*)(aFp + 4);
            __nv_bfloat16 h0, h1, l0, l1;
            split2(f0.x, h0, l0); split2(f0.y, h1, l1);
            *(__nv_bfloat162*)&smAh[0][soff + 0] = __nv_bfloat162(h0, h1);
            *(__nv_bfloat162*)&smAl[0][soff + 0] = __nv_bfloat162(l0, l1);
            split2(f0.z, h0, l0); split2(f0.w, h1, l1);
            *(__nv_bfloat162*)&smAh[0][soff + 2] = __nv_bfloat162(h0, h1);
            *(__nv_bfloat162*)&smAl[0][soff + 2] = __nv_bfloat162(l0, l1);
            split2(f1.x, h0, l0); split2(f1.y, h1, l1);
            *(__nv_bfloat162*)&smAh[0][soff + 4] = __nv_bfloat162(h0, h1);
            *(__nv_bfloat162*)&smAl[0][soff + 4] = __nv_bfloat162(l0, l1);
            split2(f1.z, h0, l0); split2(f1.w, h1, l1);
            *(__nv_bfloat162*)&smAh[0][soff + 6] = __nv_bfloat162(h0, h1);
            *(__nv_bfloat162*)&smAl[0][soff + 6] = __nv_bfloat162(l0, l1);
        } else {
            cpasync16(baseAh + soffB, aHp);
            cpasync16(baseAl + soffB, aLp);
        }
        cpasync16(baseBh + soffB, bHp);
        cpasync16(baseBl + soffB, bLp);
        CP_COMMIT();
        CP_WAIT0();
    }
    __syncthreads();

    int cur = 0;
    for (int kt = 0; kt < K_; kt += GBK) {
        const int next = kt + GBK;
        float4 pf0, pf1;
        if (next < K_) {
            // issue async copies for the next tile into the other stage
            const uint32_t sb = (uint32_t)((cur ^ 1) * STAGE_BYTES) + soffB;
            if (AF32) {
                pf0 = *(const float4*)(aFp + next);
                pf1 = *(const float4*)(aFp + next + 4);
            } else {
                cpasync16(baseAh + sb, aHp + next);
                cpasync16(baseAl + sb, aLp + next);
            }
            cpasync16(baseBh + sb, bHp + next);
            cpasync16(baseBl + sb, bLp + next);
            CP_COMMIT();
        }

        const uint32_t so = (uint32_t)(cur * STAGE_BYTES);

        // A fragments via ldmatrix.x4 (one per mt per array)
        uint32_t aH[2][4], aL[2][4];
#pragma unroll
        for (int mt = 0; mt < 2; mt++) {
            ldsm_x4(aH[mt], baseAh + so + aoff[mt]);
            ldsm_x4(aL[mt], baseAl + so + aoff[mt]);
        }

        // B fragments via ldmatrix.x4 (one per nt-pair per array) + MMAs
#pragma unroll
        for (int g = 0; g < 4; g++) {
            uint32_t bH4[4], bL4[4];
            ldsm_x4(bH4, baseBh + so + boff[g]);
            ldsm_x4(bL4, baseBl + so + boff[g]);
#pragma unroll
            for (int sub = 0; sub < 2; sub++) {
                const int nt = g * 2 + sub;
                const uint32_t bh0 = bH4[sub * 2], bh1 = bH4[sub * 2 + 1];
                const uint32_t bl0 = bL4[sub * 2], bl1 = bL4[sub * 2 + 1];
#pragma unroll
                for (int mt = 0; mt < 2; mt++) {
                    mma16816(c[mt][nt], aH[mt], bh0, bh1);
                    mma16816(c[mt][nt], aH[mt], bl0, bl1);
                    mma16816(c[mt][nt], aL[mt], bh0, bh1);
                }
            }
        }

        if (next < K_) {
            const int nst = cur ^ 1;
            if (AF32) {
                const int po = nst * GBM * SMSTRIDE;
                __nv_bfloat16 h0, h1, l0, l1;
                split2(pf0.x, h0, l0); split2(pf0.y, h1, l1);
                *(__nv_bfloat162*)&smAh[0][po + soff + 0] = __nv_bfloat162(h0, h1);
                *(__nv_bfloat162*)&smAl[0][po + soff + 0] = __nv_bfloat162(l0, l1);
                split2(pf0.z, h0, l0); split2(pf0.w, h1, l1);
                *(__nv_bfloat162*)&smAh[0][po + soff + 2] = __nv_bfloat162(h0, h1);
                *(__nv_bfloat162*)&smAl[0][po + soff + 2] = __nv_bfloat162(l0, l1);
                split2(pf1.x, h0, l0); split2(pf1.y, h1, l1);
                *(__nv_bfloat162*)&smAh[0][po + soff + 4] = __nv_bfloat162(h0, h1);
                *(__nv_bfloat162*)&smAl[0][po + soff + 4] = __nv_bfloat162(l0, l1);
                split2(pf1.z, h0, l0); split2(pf1.w, h1, l1);
                *(__nv_bfloat162*)&smAh[0][po + soff + 6] = __nv_bfloat162(h0, h1);
                *(__nv_bfloat162*)&smAl[0][po + soff + 6] = __nv_bfloat162(l0, l1);
            }
            CP_WAIT0();
            __syncthreads();
            cur = nst;
        }
    }

    // ---- epilogue ----
#pragma unroll
    for (int mt = 0; mt < 2; mt++) {
        int row0 = bm + m_off + mt * 16 + gid;
        int row1 = row0 + 8;
#pragma unroll
        for (int nt = 0; nt < 8; nt++) {
            int col = bn + n_off + nt * 8 + 2 * tig;
            float v0 = c[mt][nt][0], v1 = c[mt][nt][1];
            float v2 = c[mt][nt][2], v3 = c[mt][nt][3];
            if (EPI == 0) {
                float b0 = bias[col], b1 = bias[col + 1];
                v0 += b0; v1 += b1; v2 += b0; v3 += b1;
                v0 = v0 / (1.0f + expf(-v0));
                v1 = v1 / (1.0f + expf(-v1));
                v2 = v2 / (1.0f + expf(-v2));
                v3 = v3 / (1.0f + expf(-v3));
            } else if (EPI == 1 || EPI == 3) {
                float b0 = bias[col], b1 = bias[col + 1];
                v0 += b0; v1 += b1; v2 += b0; v3 += b1;
            } else {  // EPI == 2
                float d0 = dparam[col], d1 = dparam[col + 1];
                v0 += d0 * xg[(size_t)row0 * N + col];
                v1 += d1 * xg[(size_t)row0 * N + col + 1];
                v2 += d0 * xg[(size_t)row1 * N + col];
                v3 += d1 * xg[(size_t)row1 * N + col + 1];
            }
            if (WF32) {
                *(float2*)&C[(size_t)row0 * N + col] = make_float2(v0, v1);
                *(float2*)&C[(size_t)row1 * N + col] = make_float2(v2, v3);
            }
            if (WSPLIT) {
                __nv_bfloat16 h0, h1, h2, h3, l0, l1, l2, l3;
                split2(v0, h0, l0); split2(v1, h1, l1);
                split2(v2, h2, l2); split2(v3, h3, l3);
                *(__nv_bfloat162*)&oh[(size_t)row0 * N + col] = __nv_bfloat162(h0, h1);
                *(__nv_bfloat162*)&oh[(size_t)row1 * N + col] = __nv_bfloat162(h2, h3);
                *(__nv_bfloat162*)&ol[(size_t)row0 * N + col] = __nv_bfloat162(l0, l1);
                *(__nv_bfloat162*)&ol[(size_t)row1 * N + col] = __nv_bfloat162(l2, l3);
            }
        }
    }
}

// ---------------------------------------------------------------------------
// Chunked scan (fp32; pass3 also emits bf16 hi/lo split of states)
// ---------------------------------------------------------------------------
__global__ void scan_pass1() {
    const int n = threadIdx.x;
    const int c = blockIdx.x % CHUNKS;
    const int b = blockIdx.x / CHUNKS;
    const float dec = g_decay[n];
    const float* p = g_s + ((size_t)(b * S_ + c * CL)) * N_ + n;
    float st = 0.f;
#pragma unroll 8
    for (int k = 0; k < CL; k++)
        st = fmaf(st, dec, p[(size_t)k * N_]);
    g_chunkf[((size_t)b * CHUNKS + c) * N_ + n] = st;
}

__global__ void scan_pass2(const float* __restrict__ state0, float* __restrict__ tail) {
    const int n = threadIdx.x;
    const int b = blockIdx.x;
    const float dec = g_decay[n];
    float dl = dec;
#pragma unroll
    for (int i = 0; i < 6; i++) dl *= dl;    // dec^64
    float init = state0[(size_t)b * N_ + n];
    for (int c = 0; c < CHUNKS; c++) {
        size_t idx = ((size_t)b * CHUNKS + c) * N_ + n;
        g_init[idx] = init;
        init = fmaf(init, dl, g_chunkf[idx]);
    }
    if (tail) tail[(size_t)b * N_ + n] = init;  // state_f
}

__global__ void scan_pass3(__nv_bfloat16* __restrict__ oh,
                           __nv_bfloat16* __restrict__ ol) {
    const int n = threadIdx.x;
    const int c = blockIdx.x % CHUNKS;
    const int b = blockIdx.x / CHUNKS;
    const float dec = g_decay[n];
    float st = g_init[((size_t)b * CHUNKS + c) * N_ + n];
    const size_t base = ((size_t)(b * S_ + c * CL)) * N_ + n;
    const float* p = g_s + base;
#pragma unroll 4
    for (int k = 0; k < CL; k++) {
        st = fmaf(st, dec, p[(size_t)k * N_]);
        __nv_bfloat16 h, l;
        split2(st, h, l);
        oh[base + (size_t)k * N_] = h;
        ol[base + (size_t)k * N_] = l;
    }
}

// ---------------------------------------------------------------------------
extern "C" void kernel_launch(void* const* d_in, const int* in_sizes, int n_in,
                              void* d_out, int out_size) {
    const float* x      = (const float*)d_in[0];
    const float* state0 = (const float*)d_in[1];
    const float* W_gate = (const float*)d_in[2];
    const float* b_gate = (const float*)d_in[3];
    const float* W_sp   = (const float*)d_in[4];
    const float* b_sp   = (const float*)d_in[5];
    const float* W_out  = (const float*)d_in[6];
    const float* b_out  = (const float*)d_in[7];
    const float* A_log  = (const float*)d_in[8];
    const float* D_par  = (const float*)d_in[9];
    float* out = (float*)d_out;

    float *xg, *s;
    cudaGetSymbolAddress((void**)&xg, g_xgate);
    cudaGetSymbolAddress((void**)&s,  g_s);
    __nv_bfloat16 *ah, *al, *bh, *bl;
    __nv_bfloat16 *wgh, *wgl, *wsph, *wspl, *wspth, *wsptl, *woh, *wol;
    cudaGetSymbolAddress((void**)&ah, g_ah);
    cudaGetSymbolAddress((void**)&al, g_al);
    cudaGetSymbolAddress((void**)&bh, g_bh);
    cudaGetSymbolAddress((void**)&bl, g_bl);
    cudaGetSymbolAddress((void**)&wgh, g_wgh);
    cudaGetSymbolAddress((void**)&wgl, g_wgl);
    cudaGetSymbolAddress((void**)&wsph, g_wsph);
    cudaGetSymbolAddress((void**)&wspl, g_wspl);
    cudaGetSymbolAddress((void**)&wspth, g_wspth);
    cudaGetSymbolAddress((void**)&wsptl, g_wsptl);
    cudaGetSymbolAddress((void**)&woh, g_woh);
    cudaGetSymbolAddress((void**)&wol, g_wol);

    decay_kernel<<<D_, 256>>>(A_log);

    const int wN4 = (K_ * K_) / 4;
    dim3 tgrid(K_ / 32, K_ / 32), tblk(32, 8);

    // fused weight splits (one launch) + transposed split of W_sp
    weight_split3_kernel<<<(wN4 + 255) / 256, 256>>>(
        W_gate, W_sp, W_out, wgh, wgl, wsph, wspl, woh, wol, wN4);
    transpose_split_kernel<<<tgrid, tblk>>>(W_sp, wspth, wsptl);

    dim3 ggrid(N_ / GBN, M_ / GBM);            // (4, 128)

    // GEMM1: xg = silu(x @ W_gate^T + b_gate); A = fp32 x split in-loader;
    //        emits fp32 xg AND split(xg) -> bh/bl
    bsgemm_kernel<0, true, true, true><<<ggrid, 256>>>(
        x, (const __nv_bfloat16*)0, wgh, wgl, b_gate, (const float*)0,
        (const float*)0, xg, bh, bl, M_, D_);
    // GEMM2: s = xg @ W_sp^T + b_sp   (consumes bh/bl)
    bsgemm_kernel<1, true, false, false><<<ggrid, 256>>>(
        bh, bl, wsph, wspl, b_sp, (const float*)0, (const float*)0, s,
        (__nv_bfloat16*)0, (__nv_bfloat16*)0, M_, N_);

    // chunked scan; pass3 emits split(states) -> ah/al; state_f -> d_out tail
    float* tail = 0;
    long long need = (long long)M_ * D_ + (long long)B_ * N_;
    if ((long long)out_size >= need) tail = out + (size_t)M_ * D_;
    scan_pass1<<<B_ * CHUNKS, N_>>>();
    scan_pass2<<<B_, N_>>>(state0, tail);
    scan_pass3<<<B_ * CHUNKS, N_>>>(ah, al);

    // GEMM3: y = states @ W_sp + D_param * xg; emit ONLY split(y) -> bh/bl
    bsgemm_kernel<2, false, true, false><<<ggrid, 256>>>(
        ah, al, wspth, wsptl, (const float*)0, D_par, xg, (float*)0,
        bh, bl, M_, D_);
    // GEMM4: out = y @ W_out^T + b_out
    bsgemm_kernel<3, true, false, false><<<ggrid, 256>>>(
        bh, bl, woh, wol, b_out, (const float*)0, (const float*)0, out,
        (__nv_bfloat16*)0, (__nv_bfloat16*)0, M_, D_);
}

// round 12
// speedup vs baseline: 1.0939x; 1.0939x over previous
#include <cuda_runtime.h>
#include <cuda_bf16.h>
#include <cstdint>
#include <cstddef>
#include <math.h>

// Problem constants
#define B_ 4
#define S_ 4096
#define D_ 512
#define N_ 512
#define M_ (B_ * S_)          // 16384
#define K_ 512
#define CHUNKS 64
#define CL (S_ / CHUNKS)      // 64

// ---------------- scratch (device globals; runtime alloc forbidden) --------
__device__ float g_xgate[(size_t)M_ * D_];
__device__ float g_s[(size_t)M_ * N_];
__device__ float g_decay[N_];
__device__ float g_chunkf[(size_t)B_ * CHUNKS * N_];
__device__ float g_init[(size_t)B_ * CHUNKS * N_];

// bf16 hi/lo activation buffers (ping-pong between GEMMs) and weight splits
__device__ __nv_bfloat16 g_ah[(size_t)M_ * K_];
__device__ __nv_bfloat16 g_al[(size_t)M_ * K_];
__device__ __nv_bfloat16 g_bh[(size_t)M_ * K_];
__device__ __nv_bfloat16 g_bl[(size_t)M_ * K_];
__device__ __nv_bfloat16 g_wgh[K_ * K_], g_wgl[K_ * K_];
__device__ __nv_bfloat16 g_wsph[K_ * K_], g_wspl[K_ * K_];
__device__ __nv_bfloat16 g_wspth[K_ * K_], g_wsptl[K_ * K_];
__device__ __nv_bfloat16 g_woh[K_ * K_], g_wol[K_ * K_];

// ---------------------------------------------------------------------------
// decay[d] = exp( mean_k( -exp(A_log[d,k]) ) )
// ---------------------------------------------------------------------------
__global__ void decay_kernel(const float* __restrict__ A_log) {
    int d = blockIdx.x;
    float sum = 0.f;
    for (int k = threadIdx.x; k < N_; k += 256)
        sum += -expf(A_log[d * N_ + k]);
    __shared__ float red[256];
    red[threadIdx.x] = sum;
    __syncthreads();
    for (int s = 128; s > 0; s >>= 1) {
        if (threadIdx.x < s) red[threadIdx.x] += red[threadIdx.x + s];
        __syncthreads();
    }
    if (threadIdx.x == 0) g_decay[d] = expf(red[0] * (1.0f / (float)N_));
}

// ---------------------------------------------------------------------------
// fp32 -> bf16 hi + bf16 lo   (x ~= hi + lo, residual ~2^-17 relative)
// ---------------------------------------------------------------------------
__device__ __forceinline__ void split2(float v, __nv_bfloat16& h, __nv_bfloat16& l) {
    h = __float2bfloat16_rn(v);
    l = __float2bfloat16_rn(v - __bfloat162float(h));
}

__device__ __forceinline__ void split_store4(float4 f,
                                             __nv_bfloat16* h, __nv_bfloat16* l) {
    __nv_bfloat16 h0, h1, l0, l1;
    split2(f.x, h0, l0); split2(f.y, h1, l1);
    *(__nv_bfloat162*)(h)     = __nv_bfloat162(h0, h1);
    *(__nv_bfloat162*)(l)     = __nv_bfloat162(l0, l1);
    split2(f.z, h0, l0); split2(f.w, h1, l1);
    *(__nv_bfloat162*)(h + 2) = __nv_bfloat162(h0, h1);
    *(__nv_bfloat162*)(l + 2) = __nv_bfloat162(l0, l1);
}

__device__ __forceinline__ void split4_store(const float4 v,
                                             __nv_bfloat16* __restrict__ h,
                                             __nv_bfloat16* __restrict__ l,
                                             size_t i4) {
    split_store4(v, h + i4 * 4, l + i4 * 4);
}

// Fused split of the three square weight matrices (one launch instead of 3)
__global__ void weight_split3_kernel(const float* __restrict__ w0,
                                     const float* __restrict__ w1,
                                     const float* __restrict__ w2,
                                     __nv_bfloat16* __restrict__ h0,
                                     __nv_bfloat16* __restrict__ l0,
                                     __nv_bfloat16* __restrict__ h1,
                                     __nv_bfloat16* __restrict__ l1,
                                     __nv_bfloat16* __restrict__ h2,
                                     __nv_bfloat16* __restrict__ l2, int n4) {
    int i = blockIdx.x * blockDim.x + threadIdx.x;
    if (i >= n4) return;
    split4_store(((const float4*)w0)[i], h0, l0, (size_t)i);
    split4_store(((const float4*)w1)[i], h1, l1, (size_t)i);
    split4_store(((const float4*)w2)[i], h2, l2, (size_t)i);
}

// ---------------------------------------------------------------------------
// W_sp [N,D] -> transposed split:  out[d][n] = W_sp[n][d]  as bf16 hi/lo
// ---------------------------------------------------------------------------
__global__ void transpose_split_kernel(const float* __restrict__ in,
                                       __nv_bfloat16* __restrict__ oh,
                                       __nv_bfloat16* __restrict__ ol) {
    __shared__ float tile[32][33];
    int d0 = blockIdx.x * 32;
    int n0 = blockIdx.y * 32;
    int tx = threadIdx.x, ty = threadIdx.y;   // (32,8)
#pragma unroll
    for (int i = 0; i < 32; i += 8)
        tile[ty + i][tx] = in[(size_t)(n0 + ty + i) * K_ + d0 + tx];
    __syncthreads();
#pragma unroll
    for (int i = 0; i < 32; i += 8) {
        float v = tile[tx][ty + i];           // = in[n0+tx][d0+ty+i]
        __nv_bfloat16 h, l;
        split2(v, h, l);
        size_t o = (size_t)(d0 + ty + i) * K_ + n0 + tx;
        oh[o] = h;
        ol[o] = l;
    }
}

// ---------------------------------------------------------------------------
// bf16-split GEMM:  C[m][n] = sum_k A[m][k]*B[n][k], fp32 accum, 3-way split
// (Ah*Bh + Ah*Bl + Al*Bh). Tile 128x128x32, 256 thr = 8 warps (4m x 2n),
// warp tile 32x64, mma.sync.m16n8k16.bf16, double-buffered DYNAMIC smem
// (80 KB/CTA), cp.async gmem->smem, ldmatrix x4 operand feeds.
// Row stride 40 bf16 (80 B): 16B segs at (5r+c)%8 -> LDSM conflict-free.
// AF32:   A operand fp32 in gmem; loader splits hi/lo on the fly (regs->STS)
// EPI: 0 silu(v+bias) | 1 v+bias | 2 v+dparam[col]*xg[row,col] | 3 v+bias
// WF32:   write fp32 C ; WSPLIT: write bf16 hi/lo split to oh/ol
// ---------------------------------------------------------------------------
#define GBM 128
#define GBN 128
#define GBK 32
#define SMROW 40                       // bf16 elems per row (32 data + 8 pad)
#define STAGE_ELEMS (GBM * SMROW)      // 5120 elems
#define STAGE_BYTES (STAGE_ELEMS * 2)  // 10240 B
#define SMEM_TOTAL_B (8 * STAGE_BYTES) // 4 arrays x 2 stages = 81920 B

__device__ __forceinline__ void mma16816(float* c, const uint32_t a[4],
                                         uint32_t b0, uint32_t b1) {
    asm volatile(
        "mma.sync.aligned.m16n8k16.row.col.f32.bf16.bf16.f32 "
        "{%0,%1,%2,%3}, {%4,%5,%6,%7}, {%8,%9}, {%0,%1,%2,%3};\n"
        : "+f"(c[0]), "+f"(c[1]), "+f"(c[2]), "+f"(c[3])
        : "r"(a[0]), "r"(a[1]), "r"(a[2]), "r"(a[3]), "r"(b0), "r"(b1));
}

__device__ __forceinline__ void ldsm_x4(uint32_t* r, uint32_t addr) {
    asm volatile(
        "ldmatrix.sync.aligned.m8n8.x4.shared.b16 {%0,%1,%2,%3}, [%4];\n"
        : "=r"(r[0]), "=r"(r[1]), "=r"(r[2]), "=r"(r[3]) : "r"(addr));
}

__device__ __forceinline__ void cpasync16(uint32_t dst, const void* src) {
    asm volatile("cp.async.cg.shared.global [%0], [%1], 16;\n"
                 :: "r"(dst), "l"(src));
}
#define CP_COMMIT() asm volatile("cp.async.commit_group;\n" ::: "memory")
#define CP_WAIT0()  asm volatile("cp.async.wait_group 0;\n" ::: "memory")

template <int EPI, bool WF32, bool WSPLIT, bool AF32>
__global__ void __launch_bounds__(256)
bsgemm_kernel(const void* __restrict__ Ah_or_f32,
              const __nv_bfloat16* __restrict__ Al,
              const __nv_bfloat16* __restrict__ Bh,
              const __nv_bfloat16* __restrict__ Bl,
              const float* __restrict__ bias, const float* __restrict__ dparam,
              const float* __restrict__ xg, float* __restrict__ C,
              __nv_bfloat16* __restrict__ oh, __nv_bfloat16* __restrict__ ol,
              int M, int N) {
    extern __shared__ __nv_bfloat16 dynsm[];
    __nv_bfloat16* smAh = dynsm;                    // [2][STAGE_ELEMS]
    __nv_bfloat16* smAl = dynsm + 2 * STAGE_ELEMS;
    __nv_bfloat16* smBh = dynsm + 4 * STAGE_ELEMS;
    __nv_bfloat16* smBl = dynsm + 6 * STAGE_ELEMS;

    const int t = threadIdx.x;
    const int bm = blockIdx.y * GBM;
    const int bn = blockIdx.x * GBN;

    // loader mapping: 128 rows x 32 k; per thread 16 elems (2x16B) per array
    const int lrow = t >> 1;
    const int lk16 = (t & 1) * 16;
    const __nv_bfloat16* aHp = AF32 ? (const __nv_bfloat16*)0
        : (const __nv_bfloat16*)Ah_or_f32 + (size_t)(bm + lrow) * K_ + lk16;
    const float* aFp = AF32
        ? (const float*)Ah_or_f32 + (size_t)(bm + lrow) * K_ + lk16 : (const float*)0;
    const __nv_bfloat16* aLp = AF32 ? (const __nv_bfloat16*)0
        : Al + (size_t)(bm + lrow) * K_ + lk16;
    const __nv_bfloat16* bHp = Bh + (size_t)(bn + lrow) * K_ + lk16;
    const __nv_bfloat16* bLp = Bl + (size_t)(bn + lrow) * K_ + lk16;
    const int soff  = lrow * SMROW + lk16;          // element offset in stage
    const int soffB = soff * 2;                      // byte offset in stage

    // compute mapping
    const int wid = t >> 5;
    const int lane = t & 31;
    const int gid = lane >> 2;        // 0..7
    const int tig = lane & 3;         // 0..3
    const int m_off = (wid & 3) * 32;
    const int n_off = (wid >> 2) * 64;

    // ldmatrix per-lane byte offsets (within one stage, k-subtile 0)
    const int a_r = lane & 15;
    const int a_k = (lane >> 4) * 8;
    int aoff[2];
#pragma unroll
    for (int mt = 0; mt < 2; mt++)
        aoff[mt] = ((m_off + mt * 16 + a_r) * SMROW + a_k) * 2;
    const int b_r = (lane & 7) + ((lane >> 4) * 8);
    const int b_k = ((lane >> 3) & 1) * 8;
    int boff[4];
#pragma unroll
    for (int g = 0; g < 4; g++)
        boff[g] = ((n_off + g * 16 + b_r) * SMROW + b_k) * 2;

    const uint32_t baseAh = (uint32_t)__cvta_generic_to_shared(smAh);
    const uint32_t baseAl = (uint32_t)__cvta_generic_to_shared(smAl);
    const uint32_t baseBh = (uint32_t)__cvta_generic_to_shared(smBh);
    const uint32_t baseBl = (uint32_t)__cvta_generic_to_shared(smBl);

    float c[2][8][4];
#pragma unroll
    for (int mt = 0; mt < 2; mt++)
#pragma unroll
        for (int nt = 0; nt < 8; nt++)
#pragma unroll
            for (int r = 0; r < 4; r++) c[mt][nt][r] = 0.f;

    {   // preload chunk 0 -> stage 0
        if (AF32) {
#pragma unroll
            for (int i = 0; i < 4; i++) {
                float4 f = *(const float4*)(aFp + i * 4);
                split_store4(f, smAh + soff + i * 4, smAl + soff + i * 4);
            }
        } else {
            cpasync16(baseAh + soffB, aHp);
            cpasync16(baseAh + soffB + 16, aHp + 8);
            cpasync16(baseAl + soffB, aLp);
            cpasync16(baseAl + soffB + 16, aLp + 8);
        }
        cpasync16(baseBh + soffB, bHp);
        cpasync16(baseBh + soffB + 16, bHp + 8);
        cpasync16(baseBl + soffB, bLp);
        cpasync16(baseBl + soffB + 16, bLp + 8);
        CP_COMMIT();
        CP_WAIT0();
    }
    __syncthreads();

    int cur = 0;
    for (int kt = 0; kt < K_; kt += GBK) {
        const int next = kt + GBK;
        float4 pf[4];
        if (next < K_) {
            // issue async copies for the next tile into the other stage
            const uint32_t sb = (uint32_t)((cur ^ 1) * STAGE_BYTES) + soffB;
            if (AF32) {
#pragma unroll
                for (int i = 0; i < 4; i++)
                    pf[i] = *(const float4*)(aFp + next + i * 4);
            } else {
                cpasync16(baseAh + sb, aHp + next);
                cpasync16(baseAh + sb + 16, aHp + next + 8);
                cpasync16(baseAl + sb, aLp + next);
                cpasync16(baseAl + sb + 16, aLp + next + 8);
            }
            cpasync16(baseBh + sb, bHp + next);
            cpasync16(baseBh + sb + 16, bHp + next + 8);
            cpasync16(baseBl + sb, bLp + next);
            cpasync16(baseBl + sb + 16, bLp + next + 8);
            CP_COMMIT();
        }

        const uint32_t so = (uint32_t)(cur * STAGE_BYTES);

#pragma unroll
        for (int ksub = 0; ksub < 2; ksub++) {
            const uint32_t ko = so + ksub * 32;   // +16 elems = +32 B

            // A fragments via ldmatrix.x4 (one per mt per array)
            uint32_t aH[2][4], aL[2][4];
#pragma unroll
            for (int mt = 0; mt < 2; mt++) {
                ldsm_x4(aH[mt], baseAh + ko + aoff[mt]);
                ldsm_x4(aL[mt], baseAl + ko + aoff[mt]);
            }

            // B fragments via ldmatrix.x4 (one per nt-pair per array) + MMAs
#pragma unroll
            for (int g = 0; g < 4; g++) {
                uint32_t bH4[4], bL4[4];
                ldsm_x4(bH4, baseBh + ko + boff[g]);
                ldsm_x4(bL4, baseBl + ko + boff[g]);
#pragma unroll
                for (int sub = 0; sub < 2; sub++) {
                    const int nt = g * 2 + sub;
                    const uint32_t bh0 = bH4[sub * 2], bh1 = bH4[sub * 2 + 1];
                    const uint32_t bl0 = bL4[sub * 2], bl1 = bL4[sub * 2 + 1];
#pragma unroll
                    for (int mt = 0; mt < 2; mt++) {
                        mma16816(c[mt][nt], aH[mt], bh0, bh1);
                        mma16816(c[mt][nt], aH[mt], bl0, bl1);
                        mma16816(c[mt][nt], aL[mt], bh0, bh1);
                    }
                }
            }
        }

        if (next < K_) {
            const int nst = cur ^ 1;
            if (AF32) {
                const int po = nst * STAGE_ELEMS;
#pragma unroll
                for (int i = 0; i < 4; i++)
                    split_store4(pf[i], smAh + po + soff + i * 4,
                                 smAl + po + soff + i * 4);
            }
            CP_WAIT0();
            __syncthreads();
            cur = nst;
        }
    }

    // ---- epilogue ----
#pragma unroll
    for (int mt = 0; mt < 2; mt++) {
        int row0 = bm + m_off + mt * 16 + gid;
        int row1 = row0 + 8;
#pragma unroll
        for (int nt = 0; nt < 8; nt++) {
            int col = bn + n_off + nt * 8 + 2 * tig;
            float v0 = c[mt][nt][0], v1 = c[mt][nt][1];
            float v2 = c[mt][nt][2], v3 = c[mt][nt][3];
            if (EPI == 0) {
                float b0 = bias[col], b1 = bias[col + 1];
                v0 += b0; v1 += b1; v2 += b0; v3 += b1;
                v0 = v0 / (1.0f + expf(-v0));
                v1 = v1 / (1.0f + expf(-v1));
                v2 = v2 / (1.0f + expf(-v2));
                v3 = v3 / (1.0f + expf(-v3));
            } else if (EPI == 1 || EPI == 3) {
                float b0 = bias[col], b1 = bias[col + 1];
                v0 += b0; v1 += b1; v2 += b0; v3 += b1;
            } else {  // EPI == 2
                float d0 = dparam[col], d1 = dparam[col + 1];
                v0 += d0 * xg[(size_t)row0 * N + col];
                v1 += d1 * xg[(size_t)row0 * N + col + 1];
                v2 += d0 * xg[(size_t)row1 * N + col];
                v3 += d1 * xg[(size_t)row1 * N + col + 1];
            }
            if (WF32) {
                *(float2*)&C[(size_t)row0 * N + col] = make_float2(v0, v1);
                *(float2*)&C[(size_t)row1 * N + col] = make_float2(v2, v3);
            }
            if (WSPLIT) {
                __nv_bfloat16 h0, h1, h2, h3, l0, l1, l2, l3;
                split2(v0, h0, l0); split2(v1, h1, l1);
                split2(v2, h2, l2); split2(v3, h3, l3);
                *(__nv_bfloat162*)&oh[(size_t)row0 * N + col] = __nv_bfloat162(h0, h1);
                *(__nv_bfloat162*)&oh[(size_t)row1 * N + col] = __nv_bfloat162(h2, h3);
                *(__nv_bfloat162*)&ol[(size_t)row0 * N + col] = __nv_bfloat162(l0, l1);
                *(__nv_bfloat162*)&ol[(size_t)row1 * N + col] = __nv_bfloat162(l2, l3);
            }
        }
    }
}

// ---------------------------------------------------------------------------
// Chunked scan (fp32; pass3 also emits bf16 hi/lo split of states)
// ---------------------------------------------------------------------------
__global__ void scan_pass1() {
    const int n = threadIdx.x;
    const int c = blockIdx.x % CHUNKS;
    const int b = blockIdx.x / CHUNKS;
    const float dec = g_decay[n];
    const float* p = g_s + ((size_t)(b * S_ + c * CL)) * N_ + n;
    float st = 0.f;
#pragma unroll 8
    for (int k = 0; k < CL; k++)
        st = fmaf(st, dec, p[(size_t)k * N_]);
    g_chunkf[((size_t)b * CHUNKS + c) * N_ + n] = st;
}

__global__ void scan_pass2(const float* __restrict__ state0, float* __restrict__ tail) {
    const int n = threadIdx.x;
    const int b = blockIdx.x;
    const float dec = g_decay[n];
    float dl = dec;
#pragma unroll
    for (int i = 0; i < 6; i++) dl *= dl;    // dec^64
    float init = state0[(size_t)b * N_ + n];
    for (int c = 0; c < CHUNKS; c++) {
        size_t idx = ((size_t)b * CHUNKS + c) * N_ + n;
        g_init[idx] = init;
        init = fmaf(init, dl, g_chunkf[idx]);
    }
    if (tail) tail[(size_t)b * N_ + n] = init;  // state_f
}

__global__ void scan_pass3(__nv_bfloat16* __restrict__ oh,
                           __nv_bfloat16* __restrict__ ol) {
    const int n = threadIdx.x;
    const int c = blockIdx.x % CHUNKS;
    const int b = blockIdx.x / CHUNKS;
    const float dec = g_decay[n];
    float st = g_init[((size_t)b * CHUNKS + c) * N_ + n];
    const size_t base = ((size_t)(b * S_ + c * CL)) * N_ + n;
    const float* p = g_s + base;
#pragma unroll 4
    for (int k = 0; k < CL; k++) {
        st = fmaf(st, dec, p[(size_t)k * N_]);
        __nv_bfloat16 h, l;
        split2(st, h, l);
        oh[base + (size_t)k * N_] = h;
        ol[base + (size_t)k * N_] = l;
    }
}

// ---------------------------------------------------------------------------
extern "C" void kernel_launch(void* const* d_in, const int* in_sizes, int n_in,
                              void* d_out, int out_size) {
    const float* x      = (const float*)d_in[0];
    const float* state0 = (const float*)d_in[1];
    const float* W_gate = (const float*)d_in[2];
    const float* b_gate = (const float*)d_in[3];
    const float* W_sp   = (const float*)d_in[4];
    const float* b_sp   = (const float*)d_in[5];
    const float* W_out  = (const float*)d_in[6];
    const float* b_out  = (const float*)d_in[7];
    const float* A_log  = (const float*)d_in[8];
    const float* D_par  = (const float*)d_in[9];
    float* out = (float*)d_out;

    float *xg, *s;
    cudaGetSymbolAddress((void**)&xg, g_xgate);
    cudaGetSymbolAddress((void**)&s,  g_s);
    __nv_bfloat16 *ah, *al, *bh, *bl;
    __nv_bfloat16 *wgh, *wgl, *wsph, *wspl, *wspth, *wsptl, *woh, *wol;
    cudaGetSymbolAddress((void**)&ah, g_ah);
    cudaGetSymbolAddress((void**)&al, g_al);
    cudaGetSymbolAddress((void**)&bh, g_bh);
    cudaGetSymbolAddress((void**)&bl, g_bl);
    cudaGetSymbolAddress((void**)&wgh, g_wgh);
    cudaGetSymbolAddress((void**)&wgl, g_wgl);
    cudaGetSymbolAddress((void**)&wsph, g_wsph);
    cudaGetSymbolAddress((void**)&wspl, g_wspl);
    cudaGetSymbolAddress((void**)&wspth, g_wspth);
    cudaGetSymbolAddress((void**)&wsptl, g_wsptl);
    cudaGetSymbolAddress((void**)&woh, g_woh);
    cudaGetSymbolAddress((void**)&wol, g_wol);

    // opt-in to 80 KB dynamic smem (attribute set is not a stream op;
    // graph-capture-safe, idempotent)
    cudaFuncSetAttribute(bsgemm_kernel<0, true, true, true>,
                         cudaFuncAttributeMaxDynamicSharedMemorySize, SMEM_TOTAL_B);
    cudaFuncSetAttribute(bsgemm_kernel<1, true, false, false>,
                         cudaFuncAttributeMaxDynamicSharedMemorySize, SMEM_TOTAL_B);
    cudaFuncSetAttribute(bsgemm_kernel<2, false, true, false>,
                         cudaFuncAttributeMaxDynamicSharedMemorySize, SMEM_TOTAL_B);
    cudaFuncSetAttribute(bsgemm_kernel<3, true, false, false>,
                         cudaFuncAttributeMaxDynamicSharedMemorySize, SMEM_TOTAL_B);

    decay_kernel<<<D_, 256>>>(A_log);

    const int wN4 = (K_ * K_) / 4;
    dim3 tgrid(K_ / 32, K_ / 32), tblk(32, 8);

    // fused weight splits (one launch) + transposed split of W_sp
    weight_split3_kernel<<<(wN4 + 255) / 256, 256>>>(
        W_gate, W_sp, W_out, wgh, wgl, wsph, wspl, woh, wol, wN4);
    transpose_split_kernel<<<tgrid, tblk>>>(W_sp, wspth, wsptl);

    dim3 ggrid(N_ / GBN, M_ / GBM);            // (4, 128)

    // GEMM1: xg = silu(x @ W_gate^T + b_gate); A = fp32 x split in-loader;
    //        emits fp32 xg AND split(xg) -> bh/bl
    bsgemm_kernel<0, true, true, true><<<ggrid, 256, SMEM_TOTAL_B>>>(
        x, (const __nv_bfloat16*)0, wgh, wgl, b_gate, (const float*)0,
        (const float*)0, xg, bh, bl, M_, D_);
    // GEMM2: s = xg @ W_sp^T + b_sp   (consumes bh/bl)
    bsgemm_kernel<1, true, false, false><<<ggrid, 256, SMEM_TOTAL_B>>>(
        bh, bl, wsph, wspl, b_sp, (const float*)0, (const float*)0, s,
        (__nv_bfloat16*)0, (__nv_bfloat16*)0, M_, N_);

    // chunked scan; pass3 emits split(states) -> ah/al; state_f -> d_out tail
    float* tail = 0;
    long long need = (long long)M_ * D_ + (long long)B_ * N_;
    if ((long long)out_size >= need) tail = out + (size_t)M_ * D_;
    scan_pass1<<<B_ * CHUNKS, N_>>>();
    scan_pass2<<<B_, N_>>>(state0, tail);
    scan_pass3<<<B_ * CHUNKS, N_>>>(ah, al);

    // GEMM3: y = states @ W_sp + D_param * xg; emit ONLY split(y) -> bh/bl
    bsgemm_kernel<2, false, true, false><<<ggrid, 256, SMEM_TOTAL_B>>>(
        ah, al, wspth, wsptl, (const float*)0, D_par, xg, (float*)0,
        bh, bl, M_, D_);
    // GEMM4: out = y @ W_out^T + b_out
    bsgemm_kernel<3, true, false, false><<<ggrid, 256, SMEM_TOTAL_B>>>(
        bh, bl, woh, wol, b_out, (const float*)0, (const float*)0, out,
        (__nv_bfloat16*)0, (__nv_bfloat16*)0, M_, D_);
}